// round 14
// baseline (speedup 1.0000x reference)
#include <cuda_runtime.h>
#include <math.h>

#define NB 32
#define NA 5
#define NC 20
#define NH 64
#define NW 64
#define NT 50
#define HW (NH*NW)                  // 4096
#define CELLS_PER_B (NA*HW)         // 20480
#define NCELL (NB*CELLS_PER_B)      // 655360
#define NCH (5+NC)                  // 25
#define TPB 256
#define CPT 4                       // cells per thread
#define CPB (TPB*CPT)               // 1024 cells per block
#define NBLK (NCELL/CPB)            // 640

__device__ float  g_part[NBLK];
__device__ int    g_ticket = 0;

// sigmoid via single-MUFU tanh.approx: sigma(v) = 0.5*tanh(v/2) + 0.5
__device__ __forceinline__ float fast_sigmoid(float v) {
    float t;
    asm("tanh.approx.f32 %0, %1;" : "=f"(t) : "f"(0.5f * v));
    return fmaf(0.5f, t, 0.5f);
}

__global__ void __launch_bounds__(TPB, 4) k_all(const float* __restrict__ out,
                                                const float* __restrict__ target,
                                                const float* __restrict__ anchors,
                                                float* __restrict__ res) {
    __shared__ float4 s_box[NT];
    __shared__ float  s_thr[NT];
    __shared__ float2 s_yband[NT];     // (ylo, yhi): row-cull band
    __shared__ int    s_cellc[NT];     // by compacted slot
    __shared__ int    s_c0, s_c1, s_nfix;
    __shared__ int    s_fcell[NT];
    __shared__ float4 s_fbox[NT];
    __shared__ float  s_fga[NT], s_ftx[NT], s_fty[NT], s_ftw[NT], s_fth[NT];
    __shared__ int    s_ftcls[NT];
    __shared__ float  s_ws[TPB/32];
    __shared__ bool   s_last;

    int tid = threadIdx.x;
    int lane = tid & 31;
    int gid0 = blockIdx.x * CPB + tid * CPT;
    int bstart = blockIdx.x * CPB;
    int b = bstart / CELLS_PER_B;      // block fully inside one batch
    int within = gid0 - b * CELLS_PER_B;
    int a = within >> 12;
    int ji = within & 4095;
    int j = ji >> 6, i0 = ji & 63;

    // ---------------- per-batch target prep (ballot compaction) ----------
    float gx=0, gy=0, gw=0, gh=0, cls=0;
    bool v = false;
    int slot = 0;
    if (tid == 0) s_nfix = 0;
    if (tid < NT) {
        const float* tg = target + (size_t)(b*NT + tid)*5;
        cls = tg[0];
        float xn = tg[1], yn = tg[2], wn = tg[3], hn = tg[4];
        v = (xn > 0.0f);
        gx = xn * (float)NW; gy = yn * (float)NH;
        gw = wn * (float)NW; gh = hn * (float)NH;
    }
    if (tid < 64) {
        unsigned bal = __ballot_sync(0xffffffffu, v);
        slot = __popc(bal & ((1u << lane) - 1u));
        if (lane == 0) {
            if (tid < 32) s_c0 = __popc(bal);
            else          s_c1 = __popc(bal);
        }
    }
    int mycell = -1, gi = 0, gj = 0;
    float baw = 0.0f, bah = 0.0f, area = 0.0f;
    float4 mybox = make_float4(0,0,0,0);
    if (v) {
        mybox = make_float4(gx - 0.5f*gw, gy - 0.5f*gh,
                            gx + 0.5f*gw, gy + 0.5f*gh);
        area = gw * gh;
        // best anchor via cross-multiplied IoU comparison (no divides)
        int best = 0;
        float binter = -1.0f, buni = 1.0f;
        #pragma unroll
        for (int q = 0; q < NA; q++) {
            float aw_ = anchors[2*q], ah_ = anchors[2*q+1];
            float inter = fminf(gw, aw_) * fminf(gh, ah_);
            float uni = fmaxf(area + aw_*ah_ - inter, 1e-10f);
            if (inter * buni > binter * uni) {
                binter = inter; buni = uni; baw = aw_; bah = ah_; best = q;
            }
        }
        gi = min(max((int)floorf(gx), 0), NW-1);
        gj = min(max((int)floorf(gy), 0), NH-1);
        mycell = ((b*NA + best)*NH + gj)*NW + gi;
    }
    __syncthreads();
    int cnt = s_c0 + s_c1;
    if (v) {
        if (tid >= 32) slot += s_c0;
        s_box[slot]   = mybox;
        s_thr[slot]   = 0.375f * area;
        // sil requires pred center py within this band (AM-GM + interval
        // bound proof; 0.9 = 0.5 + 0.4 margin)
        s_yband[slot] = make_float2(gy - 0.9f*gh, gy + 0.9f*gh);
        s_cellc[slot] = mycell;
    }
    __syncthreads();
    if (v) {
        bool lw = true;                      // last-writer-wins
        for (int u = slot + 1; u < cnt; u++)
            if (s_cellc[u] == mycell) lw = false;
        if (lw && mycell >= bstart && mycell < bstart + CPB) {
            int f = atomicAdd(&s_nfix, 1);
            s_fcell[f] = mycell;
            s_fbox[f]  = mybox;
            s_fga[f]   = area;
            s_ftx[f]   = gx - (float)gi;
            s_fty[f]   = gy - (float)gj;
            s_ftw[f]   = logf(fmaxf(gw, 1e-10f) / baw);
            s_fth[f]   = logf(fmaxf(gh, 1e-10f) / bah);
            s_ftcls[f] = (int)cls;
        }
    }
    __syncthreads();
    int nfix = s_nfix;

    // ---------------- hot path: 4 cells per thread ----------------
    int base = (b*(NA*NCH) + a*NCH)*HW + ji;
    const float* p = out + base;
    float aw = anchors[2*a], ah = anchors[2*a+1];
    float pl[CPT], pr[CPT], pt[CPT], pb[CPT], pthr[CPT];
    float acc = 0.0f;
    {
        float4 A0 = *(const float4*)(p);
        float4 A1 = *(const float4*)(p + HW);
        float4 A2 = *(const float4*)(p + 2*HW);
        float4 A3 = *(const float4*)(p + 3*HW);
        float o0a[CPT] = {A0.x, A0.y, A0.z, A0.w};
        float o1a[CPT] = {A1.x, A1.y, A1.z, A1.w};
        float o2a[CPT] = {A2.x, A2.y, A2.z, A2.w};
        float o3a[CPT] = {A3.x, A3.y, A3.z, A3.w};
        #pragma unroll
        for (int c = 0; c < CPT; c++) {
            float x  = fast_sigmoid(o0a[c]);
            float y  = fast_sigmoid(o1a[c]);
            float pw = __expf(o2a[c]) * aw;
            float ph = __expf(o3a[c]) * ah;
            float px = x + (float)(i0 + c);
            float py = y + (float)j;
            pl[c] = px - 0.5f*pw;  pr[c] = px + 0.5f*pw;
            pt[c] = py - 0.5f*ph;  pb[c] = py + 0.5f*ph;
            pthr[c] = 0.375f * (pw * ph);
            float dx = x - 0.5f, dy = y - 0.5f;
            acc += 0.5f*(dx*dx + dy*dy + o2a[c]*o2a[c] + o3a[c]*o3a[c]);
        }
    }

    bool sil[CPT];
    #pragma unroll
    for (int c = 0; c < CPT; c++) sil[c] = false;
    float jf = (float)j, jf1 = (float)(j + 1);
    #pragma unroll 1
    for (int t = 0; t < cnt; t++) {
        float2 yb = s_yband[t];
        // row cull: pred center py in (j, j+1); sil impossible if band missed
        if (jf1 > yb.x && jf < yb.y) {
            float4 g = s_box[t];
            float thr = s_thr[t];
            #pragma unroll
            for (int c = 0; c < CPT; c++) {
                // exact: since pthr+thr > 0, clamping one dim suffices
                float d1 = fminf(pr[c], g.z) - fmaxf(pl[c], g.x);
                float d2 = fminf(pb[c], g.w) - fmaxf(pt[c], g.y);
                float d1c = fmaxf(d1, 0.0f);
                sil[c] = sil[c] | (fmaf(d1c, d2, -thr) > pthr[c]);
            }
        }
    }

    // conf term: load channel 4 after the loop (keeps loop-live regs low)
    {
        float4 C0 = *(const float4*)(p + 4*HW);
        float o4a[CPT] = {C0.x, C0.y, C0.z, C0.w};
        #pragma unroll
        for (int c = 0; c < CPT; c++) {
            float cf = fast_sigmoid(o4a[c]);
            acc += sil[c] ? 0.0f : 0.5f*cf*cf;
        }
    }

    // ---------------- rare path: matched-cell correction ----------------
    // Fully recomputed from global memory; NO dynamic indexing of the
    // per-cell register arrays (that forces them into local memory).
    for (int f = 0; f < nfix; f++) {
        int d = s_fcell[f] - gid0;
        if (d >= 0 && d < CPT) {
            float o0 = out[base + d];
            float o1 = out[base + d +   HW];
            float o2 = out[base + d + 2*HW];
            float o3 = out[base + d + 3*HW];
            float o4 = out[base + d + 4*HW];
            float x = fast_sigmoid(o0);
            float y = fast_sigmoid(o1);
            float conf = fast_sigmoid(o4);
            float pw = __expf(o2) * aw;
            float ph = __expf(o3) * ah;
            float parea = pw * ph;
            float px = x + (float)(i0 + d);
            float py = y + (float)j;
            float Pl = px - 0.5f*pw, Pr = px + 0.5f*pw;
            float Pt = py - 0.5f*ph, Pb = py + 0.5f*ph;
            float Pthr = 0.375f * parea;
            // re-run full (uncauged) sil screen for this single cell
            bool sild = false;
            for (int t = 0; t < cnt; t++) {
                float4 gg = s_box[t];
                float d1 = fminf(Pr, gg.z) - fmaxf(Pl, gg.x);
                float d2 = fminf(Pb, gg.w) - fmaxf(Pt, gg.y);
                float d1c = fmaxf(d1, 0.0f);
                sild = sild | (fmaf(d1c, d2, -s_thr[t]) > Pthr);
            }
            float ddx = x - 0.5f, ddy = y - 0.5f;
            float D = 0.5f*(ddx*ddx + ddy*ddy + o2*o2 + o3*o3)
                    + (sild ? 0.0f : 0.5f*conf*conf);
            float4 g = s_fbox[f];
            float l  = fmaxf(Pl, g.x);
            float tt = fmaxf(Pt, g.y);
            float rr = fminf(Pr, g.z);
            float bb = fminf(Pb, g.w);
            float inter = fmaxf(rr - l, 0.0f) * fmaxf(bb - tt, 0.0f);
            float uni = fmaxf(parea + s_fga[f] - inter, 1e-10f);
            float tconf = __fdividef(inter, uni);
            int cbase = base + d + 5*HW;
            float m = -1e30f;
            #pragma unroll
            for (int q = 0; q < NC; q++)
                m = fmaxf(m, out[cbase + q*HW]);
            float sum = 0.0f;
            #pragma unroll
            for (int q = 0; q < NC; q++)
                sum += __expf(out[cbase + q*HW] - m);
            float lcls = m + logf(sum) - out[cbase + s_ftcls[f]*HW];
            float dx = x - s_ftx[f], dy = y - s_fty[f];
            float dw = o2 - s_ftw[f], dh = o3 - s_fth[f];
            float dc = conf - tconf;
            acc += 0.5f*(dx*dx + dy*dy + dw*dw + dh*dh + 5.0f*(dc*dc))
                 + lcls - D;
        }
    }

    // ---------------- reduction ----------------
    float vv = acc;
    #pragma unroll
    for (int o = 16; o > 0; o >>= 1)
        vv += __shfl_down_sync(0xffffffffu, vv, o);
    int w = tid >> 5;
    if (lane == 0) s_ws[w] = vv;
    __syncthreads();
    if (w == 0) {
        vv = (lane < TPB/32) ? s_ws[lane] : 0.0f;
        #pragma unroll
        for (int o = 4; o > 0; o >>= 1)
            vv += __shfl_down_sync(0xffffffffu, vv, o);
        if (lane == 0) g_part[blockIdx.x] = vv;
    }

    // arrival ticket: last block sums the 640 partials in double
    __threadfence();
    __syncthreads();
    if (tid == 0) {
        int old = atomicAdd(&g_ticket, 1);
        s_last = (old == NBLK - 1);
    }
    __syncthreads();
    if (s_last) {
        double dacc = 0.0;
        for (int idx = tid; idx < NBLK; idx += TPB) dacc += (double)g_part[idx];
        #pragma unroll
        for (int o = 16; o > 0; o >>= 1)
            dacc += __shfl_down_sync(0xffffffffu, dacc, o);
        __shared__ double s_dw[TPB/32];
        if (lane == 0) s_dw[w] = dacc;
        __syncthreads();
        if (w == 0) {
            dacc = (lane < TPB/32) ? s_dw[lane] : 0.0;
            #pragma unroll
            for (int o = 4; o > 0; o >>= 1)
                dacc += __shfl_down_sync(0xffffffffu, dacc, o);
            if (lane == 0) { res[0] = (float)dacc; g_ticket = 0; }
        }
    }
}

extern "C" void kernel_launch(void* const* d_in, const int* in_sizes, int n_in,
                              void* d_out, int out_size) {
    const float* output  = (const float*)d_in[0];
    const float* target  = (const float*)d_in[1];
    const float* anchors = (const float*)d_in[2];
    float* res = (float*)d_out;
    (void)in_sizes; (void)n_in; (void)out_size;

    k_all<<<NBLK, TPB>>>(output, target, anchors, res);
}

// round 15
// speedup vs baseline: 1.0273x; 1.0273x over previous
#include <cuda_runtime.h>
#include <math.h>

#define NB 32
#define NA 5
#define NC 20
#define NH 64
#define NW 64
#define NT 50
#define HW (NH*NW)                  // 4096
#define CELLS_PER_B (NA*HW)         // 20480
#define NCELL (NB*CELLS_PER_B)      // 655360
#define NCH (5+NC)                  // 25
#define TPB 256
#define CPT 4                       // cells per thread
#define CPB (TPB*CPT)               // 1024 cells per block (= 16 rows)
#define NBLK (NCELL/CPB)            // 640

__device__ float  g_part[NBLK];
__device__ int    g_ticket = 0;

// sigmoid via single-MUFU tanh.approx: sigma(v) = 0.5*tanh(v/2) + 0.5
__device__ __forceinline__ float fast_sigmoid(float v) {
    float t;
    asm("tanh.approx.f32 %0, %1;" : "=f"(t) : "f"(0.5f * v));
    return fmaf(0.5f, t, 0.5f);
}

__global__ void __launch_bounds__(TPB, 4) k_all(const float* __restrict__ out,
                                                const float* __restrict__ target,
                                                const float* __restrict__ anchors,
                                                float* __restrict__ res) {
    // filtered sil list (block-level y-intersection applied)
    __shared__ float4 s_box[NT];       // (gl, gt, gr, gb)
    __shared__ float4 s_meta[NT];      // (ylo, yhi, thr, unused)
    // full list bookkeeping for last-writer-wins / fix list
    __shared__ int    s_cellc[NT];
    __shared__ int    s_c0, s_c1, s_nsil, s_nfix;
    __shared__ int    s_fcell[NT];
    __shared__ float4 s_fbox[NT];
    __shared__ float  s_fga[NT], s_ftx[NT], s_fty[NT], s_ftw[NT], s_fth[NT];
    __shared__ int    s_ftcls[NT];
    __shared__ float  s_ws[TPB/32];
    __shared__ bool   s_last;

    int tid = threadIdx.x;
    int lane = tid & 31;
    int gid0 = blockIdx.x * CPB + tid * CPT;
    int bstart = blockIdx.x * CPB;
    int b = bstart / CELLS_PER_B;      // block fully inside one batch
    int within = gid0 - b * CELLS_PER_B;
    int a = within >> 12;
    int ji = within & 4095;
    int j = ji >> 6, i0 = ji & 63;
    // block's row window: 16 rows starting at j0blk (single anchor region)
    int ji0 = (bstart - b * CELLS_PER_B) & 4095;
    float j0blk = (float)(ji0 >> 6);
    float j1blk = j0blk + 16.0f;

    // ---------------- per-batch target prep (ballot compaction) ----------
    float gx=0, gy=0, gw=0, gh=0, cls=0;
    bool v = false;
    int slot = 0;
    if (tid == 0) { s_nfix = 0; s_nsil = 0; }
    if (tid < NT) {
        const float* tg = target + (size_t)(b*NT + tid)*5;
        cls = tg[0];
        float xn = tg[1], yn = tg[2], wn = tg[3], hn = tg[4];
        v = (xn > 0.0f);
        gx = xn * (float)NW; gy = yn * (float)NH;
        gw = wn * (float)NW; gh = hn * (float)NH;
    }
    if (tid < 64) {
        unsigned bal = __ballot_sync(0xffffffffu, v);
        slot = __popc(bal & ((1u << lane) - 1u));
        if (lane == 0) {
            if (tid < 32) s_c0 = __popc(bal);
            else          s_c1 = __popc(bal);
        }
    }
    int mycell = -1, gi = 0, gj = 0;
    float baw = 0.0f, bah = 0.0f, area = 0.0f;
    float4 mybox = make_float4(0,0,0,0);
    float ylo = 0.0f, yhi = 0.0f;
    if (v) {
        mybox = make_float4(gx - 0.5f*gw, gy - 0.5f*gh,
                            gx + 0.5f*gw, gy + 0.5f*gh);
        area = gw * gh;
        // sil requires pred center py within this band (AM-GM + interval
        // bound proof; 0.9 = 0.5 + 0.4 margin)
        ylo = gy - 0.9f*gh;  yhi = gy + 0.9f*gh;
        // best anchor via cross-multiplied IoU comparison (no divides)
        int best = 0;
        float binter = -1.0f, buni = 1.0f;
        #pragma unroll
        for (int q = 0; q < NA; q++) {
            float aw_ = anchors[2*q], ah_ = anchors[2*q+1];
            float inter = fminf(gw, aw_) * fminf(gh, ah_);
            float uni = fmaxf(area + aw_*ah_ - inter, 1e-10f);
            if (inter * buni > binter * uni) {
                binter = inter; buni = uni; baw = aw_; bah = ah_; best = q;
            }
        }
        gi = min(max((int)floorf(gx), 0), NW-1);
        gj = min(max((int)floorf(gy), 0), NH-1);
        mycell = ((b*NA + best)*NH + gj)*NW + gi;
    }
    __syncthreads();
    int cnt = s_c0 + s_c1;
    if (v) {
        if (tid >= 32) slot += s_c0;
        s_cellc[slot] = mycell;
        // block-level y filter: this target can trigger sil in this block
        // only if its band intersects rows [j0blk, j0blk+16)
        if (j1blk > ylo && j0blk < yhi) {
            int s2 = atomicAdd(&s_nsil, 1);
            s_box[s2]  = mybox;
            s_meta[s2] = make_float4(ylo, yhi, 0.375f * area, 0.0f);
        }
    }
    __syncthreads();
    if (v) {
        bool lw = true;                      // last-writer-wins
        for (int u = slot + 1; u < cnt; u++)
            if (s_cellc[u] == mycell) lw = false;
        if (lw && mycell >= bstart && mycell < bstart + CPB) {
            int f = atomicAdd(&s_nfix, 1);
            s_fcell[f] = mycell;
            s_fbox[f]  = mybox;
            s_fga[f]   = area;
            s_ftx[f]   = gx - (float)gi;
            s_fty[f]   = gy - (float)gj;
            s_ftw[f]   = logf(fmaxf(gw, 1e-10f) / baw);
            s_fth[f]   = logf(fmaxf(gh, 1e-10f) / bah);
            s_ftcls[f] = (int)cls;
        }
    }
    __syncthreads();
    int nfix = s_nfix;
    int nsil = s_nsil;

    // ---------------- hot path: 4 cells per thread ----------------
    int base = (b*(NA*NCH) + a*NCH)*HW + ji;
    const float* p = out + base;
    float aw = anchors[2*a], ah = anchors[2*a+1];
    float pl[CPT], pr[CPT], pt[CPT], pb[CPT], pthr[CPT];
    float acc = 0.0f;
    {
        float4 A0 = *(const float4*)(p);
        float4 A1 = *(const float4*)(p + HW);
        float4 A2 = *(const float4*)(p + 2*HW);
        float4 A3 = *(const float4*)(p + 3*HW);
        float o0a[CPT] = {A0.x, A0.y, A0.z, A0.w};
        float o1a[CPT] = {A1.x, A1.y, A1.z, A1.w};
        float o2a[CPT] = {A2.x, A2.y, A2.z, A2.w};
        float o3a[CPT] = {A3.x, A3.y, A3.z, A3.w};
        #pragma unroll
        for (int c = 0; c < CPT; c++) {
            float x  = fast_sigmoid(o0a[c]);
            float y  = fast_sigmoid(o1a[c]);
            float pw = __expf(o2a[c]) * aw;
            float ph = __expf(o3a[c]) * ah;
            float px = x + (float)(i0 + c);
            float py = y + (float)j;
            pl[c] = px - 0.5f*pw;  pr[c] = px + 0.5f*pw;
            pt[c] = py - 0.5f*ph;  pb[c] = py + 0.5f*ph;
            pthr[c] = 0.375f * (pw * ph);
            float dx = x - 0.5f, dy = y - 0.5f;
            acc += 0.5f*(dx*dx + dy*dy + o2a[c]*o2a[c] + o3a[c]*o3a[c]);
        }
    }

    bool sil[CPT];
    #pragma unroll
    for (int c = 0; c < CPT; c++) sil[c] = false;
    float jf = (float)j, jf1 = (float)(j + 1);
    #pragma unroll 2
    for (int t = 0; t < nsil; t++) {
        float4 meta = s_meta[t];
        // row cull: pred center py in (j, j+1); sil impossible if band missed
        if (jf1 > meta.x && jf < meta.y) {
            float4 g = s_box[t];
            float thr = meta.z;
            #pragma unroll
            for (int c = 0; c < CPT; c++) {
                // exact: since pthr+thr > 0, clamping one dim suffices
                float d1 = fminf(pr[c], g.z) - fmaxf(pl[c], g.x);
                float d2 = fminf(pb[c], g.w) - fmaxf(pt[c], g.y);
                float d1c = fmaxf(d1, 0.0f);
                sil[c] = sil[c] | (fmaf(d1c, d2, -thr) > pthr[c]);
            }
        }
    }

    // conf term: load channel 4 after the loop (keeps loop-live regs low)
    {
        float4 C0 = *(const float4*)(p + 4*HW);
        float o4a[CPT] = {C0.x, C0.y, C0.z, C0.w};
        #pragma unroll
        for (int c = 0; c < CPT; c++) {
            float cf = fast_sigmoid(o4a[c]);
            acc += sil[c] ? 0.0f : 0.5f*cf*cf;
        }
    }

    // ---------------- rare path: matched-cell correction ----------------
    // Fully recomputed from global memory; NO dynamic indexing of the
    // per-cell register arrays. The filtered sil list is exact for every
    // cell in this block (block-level band proof), so use it here too.
    for (int f = 0; f < nfix; f++) {
        int d = s_fcell[f] - gid0;
        if (d >= 0 && d < CPT) {
            float o0 = out[base + d];
            float o1 = out[base + d +   HW];
            float o2 = out[base + d + 2*HW];
            float o3 = out[base + d + 3*HW];
            float o4 = out[base + d + 4*HW];
            float x = fast_sigmoid(o0);
            float y = fast_sigmoid(o1);
            float conf = fast_sigmoid(o4);
            float pw = __expf(o2) * aw;
            float ph = __expf(o3) * ah;
            float parea = pw * ph;
            float px = x + (float)(i0 + d);
            float py = y + (float)j;
            float Pl = px - 0.5f*pw, Pr = px + 0.5f*pw;
            float Pt = py - 0.5f*ph, Pb = py + 0.5f*ph;
            float Pthr = 0.375f * parea;
            bool sild = false;
            for (int t = 0; t < nsil; t++) {
                float4 gg = s_box[t];
                float d1 = fminf(Pr, gg.z) - fmaxf(Pl, gg.x);
                float d2 = fminf(Pb, gg.w) - fmaxf(Pt, gg.y);
                float d1c = fmaxf(d1, 0.0f);
                sild = sild | (fmaf(d1c, d2, -s_meta[t].z) > Pthr);
            }
            float ddx = x - 0.5f, ddy = y - 0.5f;
            float D = 0.5f*(ddx*ddx + ddy*ddy + o2*o2 + o3*o3)
                    + (sild ? 0.0f : 0.5f*conf*conf);
            float4 g = s_fbox[f];
            float l  = fmaxf(Pl, g.x);
            float tt = fmaxf(Pt, g.y);
            float rr = fminf(Pr, g.z);
            float bb = fminf(Pb, g.w);
            float inter = fmaxf(rr - l, 0.0f) * fmaxf(bb - tt, 0.0f);
            float uni = fmaxf(parea + s_fga[f] - inter, 1e-10f);
            float tconf = __fdividef(inter, uni);
            int cbase = base + d + 5*HW;
            float m = -1e30f;
            #pragma unroll
            for (int q = 0; q < NC; q++)
                m = fmaxf(m, out[cbase + q*HW]);
            float sum = 0.0f;
            #pragma unroll
            for (int q = 0; q < NC; q++)
                sum += __expf(out[cbase + q*HW] - m);
            float lcls = m + logf(sum) - out[cbase + s_ftcls[f]*HW];
            float dx = x - s_ftx[f], dy = y - s_fty[f];
            float dw = o2 - s_ftw[f], dh = o3 - s_fth[f];
            float dc = conf - tconf;
            acc += 0.5f*(dx*dx + dy*dy + dw*dw + dh*dh + 5.0f*(dc*dc))
                 + lcls - D;
        }
    }

    // ---------------- reduction ----------------
    float vv = acc;
    #pragma unroll
    for (int o = 16; o > 0; o >>= 1)
        vv += __shfl_down_sync(0xffffffffu, vv, o);
    int w = tid >> 5;
    if (lane == 0) s_ws[w] = vv;
    __syncthreads();
    if (w == 0) {
        vv = (lane < TPB/32) ? s_ws[lane] : 0.0f;
        #pragma unroll
        for (int o = 4; o > 0; o >>= 1)
            vv += __shfl_down_sync(0xffffffffu, vv, o);
        if (lane == 0) g_part[blockIdx.x] = vv;
    }

    // arrival ticket: last block sums the 640 partials in double
    __threadfence();
    __syncthreads();
    if (tid == 0) {
        int old = atomicAdd(&g_ticket, 1);
        s_last = (old == NBLK - 1);
    }
    __syncthreads();
    if (s_last) {
        double dacc = 0.0;
        for (int idx = tid; idx < NBLK; idx += TPB) dacc += (double)g_part[idx];
        #pragma unroll
        for (int o = 16; o > 0; o >>= 1)
            dacc += __shfl_down_sync(0xffffffffu, dacc, o);
        __shared__ double s_dw[TPB/32];
        if (lane == 0) s_dw[w] = dacc;
        __syncthreads();
        if (w == 0) {
            dacc = (lane < TPB/32) ? s_dw[lane] : 0.0;
            #pragma unroll
            for (int o = 4; o > 0; o >>= 1)
                dacc += __shfl_down_sync(0xffffffffu, dacc, o);
            if (lane == 0) { res[0] = (float)dacc; g_ticket = 0; }
        }
    }
}

extern "C" void kernel_launch(void* const* d_in, const int* in_sizes, int n_in,
                              void* d_out, int out_size) {
    const float* output  = (const float*)d_in[0];
    const float* target  = (const float*)d_in[1];
    const float* anchors = (const float*)d_in[2];
    float* res = (float*)d_out;
    (void)in_sizes; (void)n_in; (void)out_size;

    k_all<<<NBLK, TPB>>>(output, target, anchors, res);
}

// round 16
// speedup vs baseline: 1.1382x; 1.1080x over previous
#include <cuda_runtime.h>
#include <math.h>

#define NB 32
#define NA 5
#define NC 20
#define NH 64
#define NW 64
#define NT 50
#define HW (NH*NW)                  // 4096
#define CELLS_PER_B (NA*HW)         // 20480
#define NCELL (NB*CELLS_PER_B)      // 655360
#define NCH (5+NC)                  // 25
#define TPB 256
#define CPT 4                       // cells per thread
#define CPB (TPB*CPT)               // 1024 cells per block (= 16 rows)
#define NBLK (NCELL/CPB)            // 640

__device__ float  g_part[NBLK];
__device__ int    g_ticket = 0;

// sigmoid via single-MUFU tanh.approx: sigma(v) = 0.5*tanh(v/2) + 0.5
__device__ __forceinline__ float fast_sigmoid(float v) {
    float t;
    asm("tanh.approx.f32 %0, %1;" : "=f"(t) : "f"(0.5f * v));
    return fmaf(0.5f, t, 0.5f);
}

__global__ void __launch_bounds__(TPB, 5) k_all(const float* __restrict__ out,
                                                const float* __restrict__ target,
                                                const float* __restrict__ anchors,
                                                float* __restrict__ res) {
    // filtered sil list (block-level y-intersection applied)
    __shared__ float4 s_box[NT];       // (gl, gt, gr, gb)
    __shared__ float4 s_meta[NT];      // (ylo, yhi, thr, unused)
    // full list bookkeeping for last-writer-wins / fix list
    __shared__ int    s_cellc[NT];
    __shared__ int    s_c0, s_c1, s_nsil, s_nfix;
    __shared__ int    s_fcell[NT];
    __shared__ float4 s_fbox[NT];
    __shared__ float  s_fga[NT], s_ftx[NT], s_fty[NT], s_ftw[NT], s_fth[NT];
    __shared__ int    s_ftcls[NT];
    __shared__ float  s_ws[TPB/32];
    __shared__ bool   s_last;

    int tid = threadIdx.x;
    int lane = tid & 31;
    int gid0 = blockIdx.x * CPB + tid * CPT;
    int bstart = blockIdx.x * CPB;
    int b = bstart / CELLS_PER_B;      // block fully inside one batch
    int within = gid0 - b * CELLS_PER_B;
    int a = within >> 12;
    int ji = within & 4095;
    int j = ji >> 6, i0 = ji & 63;
    // block's row window: 16 rows starting at j0blk (single anchor region)
    int ji0 = (bstart - b * CELLS_PER_B) & 4095;
    float j0blk = (float)(ji0 >> 6);
    float j1blk = j0blk + 16.0f;

    // ---------------- per-batch target prep (ballot compaction) ----------
    float gx=0, gy=0, gw=0, gh=0, cls=0;
    bool v = false;
    int slot = 0;
    if (tid == 0) { s_nfix = 0; s_nsil = 0; }
    if (tid < NT) {
        const float* tg = target + (size_t)(b*NT + tid)*5;
        cls = tg[0];
        float xn = tg[1], yn = tg[2], wn = tg[3], hn = tg[4];
        v = (xn > 0.0f);
        gx = xn * (float)NW; gy = yn * (float)NH;
        gw = wn * (float)NW; gh = hn * (float)NH;
    }
    if (tid < 64) {
        unsigned bal = __ballot_sync(0xffffffffu, v);
        slot = __popc(bal & ((1u << lane) - 1u));
        if (lane == 0) {
            if (tid < 32) s_c0 = __popc(bal);
            else          s_c1 = __popc(bal);
        }
    }
    int mycell = -1, gi = 0, gj = 0;
    float baw = 0.0f, bah = 0.0f, area = 0.0f;
    float4 mybox = make_float4(0,0,0,0);
    float ylo = 0.0f, yhi = 0.0f;
    if (v) {
        mybox = make_float4(gx - 0.5f*gw, gy - 0.5f*gh,
                            gx + 0.5f*gw, gy + 0.5f*gh);
        area = gw * gh;
        // sil requires pred center py within this band (AM-GM + interval
        // bound proof; 0.9 = 0.5 + 0.4 margin)
        ylo = gy - 0.9f*gh;  yhi = gy + 0.9f*gh;
        // best anchor via cross-multiplied IoU comparison (no divides)
        int best = 0;
        float binter = -1.0f, buni = 1.0f;
        #pragma unroll
        for (int q = 0; q < NA; q++) {
            float aw_ = anchors[2*q], ah_ = anchors[2*q+1];
            float inter = fminf(gw, aw_) * fminf(gh, ah_);
            float uni = fmaxf(area + aw_*ah_ - inter, 1e-10f);
            if (inter * buni > binter * uni) {
                binter = inter; buni = uni; baw = aw_; bah = ah_; best = q;
            }
        }
        gi = min(max((int)floorf(gx), 0), NW-1);
        gj = min(max((int)floorf(gy), 0), NH-1);
        mycell = ((b*NA + best)*NH + gj)*NW + gi;
    }
    __syncthreads();
    int cnt = s_c0 + s_c1;
    if (v) {
        if (tid >= 32) slot += s_c0;
        s_cellc[slot] = mycell;
        // block-level y filter: this target can trigger sil in this block
        // only if its band intersects rows [j0blk, j0blk+16)
        if (j1blk > ylo && j0blk < yhi) {
            int s2 = atomicAdd(&s_nsil, 1);
            s_box[s2]  = mybox;
            s_meta[s2] = make_float4(ylo, yhi, 0.375f * area, 0.0f);
        }
    }
    __syncthreads();
    if (v) {
        bool lw = true;                      // last-writer-wins
        for (int u = slot + 1; u < cnt; u++)
            if (s_cellc[u] == mycell) lw = false;
        if (lw && mycell >= bstart && mycell < bstart + CPB) {
            int f = atomicAdd(&s_nfix, 1);
            s_fcell[f] = mycell;
            s_fbox[f]  = mybox;
            s_fga[f]   = area;
            s_ftx[f]   = gx - (float)gi;
            s_fty[f]   = gy - (float)gj;
            s_ftw[f]   = __logf(fmaxf(gw, 1e-10f) / baw);
            s_fth[f]   = __logf(fmaxf(gh, 1e-10f) / bah);
            s_ftcls[f] = (int)cls;
        }
    }
    __syncthreads();
    int nfix = s_nfix;
    int nsil = s_nsil;

    // ---------------- hot path: 4 cells per thread ----------------
    int base = (b*(NA*NCH) + a*NCH)*HW + ji;
    const float* p = out + base;
    float aw = anchors[2*a], ah = anchors[2*a+1];
    float pl[CPT], pr[CPT], pt[CPT], pb[CPT], pthr[CPT];
    float acc = 0.0f;
    {
        float4 A0 = *(const float4*)(p);
        float4 A1 = *(const float4*)(p + HW);
        float4 A2 = *(const float4*)(p + 2*HW);
        float4 A3 = *(const float4*)(p + 3*HW);
        float o0a[CPT] = {A0.x, A0.y, A0.z, A0.w};
        float o1a[CPT] = {A1.x, A1.y, A1.z, A1.w};
        float o2a[CPT] = {A2.x, A2.y, A2.z, A2.w};
        float o3a[CPT] = {A3.x, A3.y, A3.z, A3.w};
        #pragma unroll
        for (int c = 0; c < CPT; c++) {
            float x  = fast_sigmoid(o0a[c]);
            float y  = fast_sigmoid(o1a[c]);
            float pw = __expf(o2a[c]) * aw;
            float ph = __expf(o3a[c]) * ah;
            float px = x + (float)(i0 + c);
            float py = y + (float)j;
            pl[c] = px - 0.5f*pw;  pr[c] = px + 0.5f*pw;
            pt[c] = py - 0.5f*ph;  pb[c] = py + 0.5f*ph;
            pthr[c] = 0.375f * (pw * ph);
            float dx = x - 0.5f, dy = y - 0.5f;
            acc += 0.5f*(dx*dx + dy*dy + o2a[c]*o2a[c] + o3a[c]*o3a[c]);
        }
    }

    bool sil[CPT];
    #pragma unroll
    for (int c = 0; c < CPT; c++) sil[c] = false;
    float jf = (float)j, jf1 = (float)(j + 1);
    #pragma unroll 2
    for (int t = 0; t < nsil; t++) {
        float4 meta = s_meta[t];
        // row cull: pred center py in (j, j+1); sil impossible if band missed
        if (jf1 > meta.x && jf < meta.y) {
            float4 g = s_box[t];
            float thr = meta.z;
            #pragma unroll
            for (int c = 0; c < CPT; c++) {
                // exact: since pthr+thr > 0, clamping one dim suffices
                float d1 = fminf(pr[c], g.z) - fmaxf(pl[c], g.x);
                float d2 = fminf(pb[c], g.w) - fmaxf(pt[c], g.y);
                float d1c = fmaxf(d1, 0.0f);
                sil[c] = sil[c] | (fmaf(d1c, d2, -thr) > pthr[c]);
            }
        }
    }

    // conf term: load channel 4 after the loop (keeps loop-live regs low)
    {
        float4 C0 = *(const float4*)(p + 4*HW);
        float o4a[CPT] = {C0.x, C0.y, C0.z, C0.w};
        #pragma unroll
        for (int c = 0; c < CPT; c++) {
            float cf = fast_sigmoid(o4a[c]);
            acc += sil[c] ? 0.0f : 0.5f*cf*cf;
        }
    }

    // ---------------- rare path: matched-cell correction ----------------
    // Fully recomputed from global memory; NO dynamic indexing of the
    // per-cell register arrays. The filtered sil list is exact for every
    // cell in this block (block-level band proof), so use it here too.
    for (int f = 0; f < nfix; f++) {
        int d = s_fcell[f] - gid0;
        if (d >= 0 && d < CPT) {
            float o0 = out[base + d];
            float o1 = out[base + d +   HW];
            float o2 = out[base + d + 2*HW];
            float o3 = out[base + d + 3*HW];
            float o4 = out[base + d + 4*HW];
            float x = fast_sigmoid(o0);
            float y = fast_sigmoid(o1);
            float conf = fast_sigmoid(o4);
            float pw = __expf(o2) * aw;
            float ph = __expf(o3) * ah;
            float parea = pw * ph;
            float px = x + (float)(i0 + d);
            float py = y + (float)j;
            float Pl = px - 0.5f*pw, Pr = px + 0.5f*pw;
            float Pt = py - 0.5f*ph, Pb = py + 0.5f*ph;
            float Pthr = 0.375f * parea;
            bool sild = false;
            for (int t = 0; t < nsil; t++) {
                float4 gg = s_box[t];
                float d1 = fminf(Pr, gg.z) - fmaxf(Pl, gg.x);
                float d2 = fminf(Pb, gg.w) - fmaxf(Pt, gg.y);
                float d1c = fmaxf(d1, 0.0f);
                sild = sild | (fmaf(d1c, d2, -s_meta[t].z) > Pthr);
            }
            float ddx = x - 0.5f, ddy = y - 0.5f;
            float D = 0.5f*(ddx*ddx + ddy*ddy + o2*o2 + o3*o3)
                    + (sild ? 0.0f : 0.5f*conf*conf);
            float4 g = s_fbox[f];
            float l  = fmaxf(Pl, g.x);
            float tt = fmaxf(Pt, g.y);
            float rr = fminf(Pr, g.z);
            float bb = fminf(Pb, g.w);
            float inter = fmaxf(rr - l, 0.0f) * fmaxf(bb - tt, 0.0f);
            float uni = fmaxf(parea + s_fga[f] - inter, 1e-10f);
            float tconf = __fdividef(inter, uni);
            int cbase = base + d + 5*HW;
            float m = -1e30f;
            #pragma unroll
            for (int q = 0; q < NC; q++)
                m = fmaxf(m, out[cbase + q*HW]);
            float sum = 0.0f;
            #pragma unroll
            for (int q = 0; q < NC; q++)
                sum += __expf(out[cbase + q*HW] - m);
            float lcls = m + __logf(sum) - out[cbase + s_ftcls[f]*HW];
            float dx = x - s_ftx[f], dy = y - s_fty[f];
            float dw = o2 - s_ftw[f], dh = o3 - s_fth[f];
            float dc = conf - tconf;
            acc += 0.5f*(dx*dx + dy*dy + dw*dw + dh*dh + 5.0f*(dc*dc))
                 + lcls - D;
        }
    }

    // ---------------- reduction ----------------
    float vv = acc;
    #pragma unroll
    for (int o = 16; o > 0; o >>= 1)
        vv += __shfl_down_sync(0xffffffffu, vv, o);
    int w = tid >> 5;
    if (lane == 0) s_ws[w] = vv;
    __syncthreads();
    if (w == 0) {
        vv = (lane < TPB/32) ? s_ws[lane] : 0.0f;
        #pragma unroll
        for (int o = 4; o > 0; o >>= 1)
            vv += __shfl_down_sync(0xffffffffu, vv, o);
        if (lane == 0) g_part[blockIdx.x] = vv;
    }

    // arrival ticket: last block sums the 640 partials in double
    __threadfence();
    __syncthreads();
    if (tid == 0) {
        int old = atomicAdd(&g_ticket, 1);
        s_last = (old == NBLK - 1);
    }
    __syncthreads();
    if (s_last) {
        double dacc = 0.0;
        for (int idx = tid; idx < NBLK; idx += TPB) dacc += (double)g_part[idx];
        #pragma unroll
        for (int o = 16; o > 0; o >>= 1)
            dacc += __shfl_down_sync(0xffffffffu, dacc, o);
        __shared__ double s_dw[TPB/32];
        if (lane == 0) s_dw[w] = dacc;
        __syncthreads();
        if (w == 0) {
            dacc = (lane < TPB/32) ? s_dw[lane] : 0.0;
            #pragma unroll
            for (int o = 4; o > 0; o >>= 1)
                dacc += __shfl_down_sync(0xffffffffu, dacc, o);
            if (lane == 0) { res[0] = (float)dacc; g_ticket = 0; }
        }
    }
}

extern "C" void kernel_launch(void* const* d_in, const int* in_sizes, int n_in,
                              void* d_out, int out_size) {
    const float* output  = (const float*)d_in[0];
    const float* target  = (const float*)d_in[1];
    const float* anchors = (const float*)d_in[2];
    float* res = (float*)d_out;
    (void)in_sizes; (void)n_in; (void)out_size;

    k_all<<<NBLK, TPB>>>(output, target, anchors, res);
}